// round 12
// baseline (speedup 1.0000x reference)
#include <cuda_runtime.h>
#include <math.h>

#define NEGO 1024
#define NEDGE 49152
#define MM 6
#define HID 256
#define HH 128
#define NH 8
#define NM (NEGO*MM)
#define LNEPS 1e-5f

typedef unsigned long long ull;
union F2U { ull u; float2 f; };

__device__ __forceinline__ void fma2(ull &d, ull a, ull b){
    asm("fma.rn.f32x2 %0, %1, %2, %0;" : "+l"(d) : "l"(a), "l"(b));
}
__device__ __forceinline__ void mul2(ull &d, ull s){
    asm("mul.rn.f32x2 %0, %0, %1;" : "+l"(d) : "l"(s));
}
__device__ __forceinline__ ull pack2(float x, float y){
    ull r; asm("mov.b64 %0, {%1,%2};" : "=l"(r) : "f"(x), "f"(y)); return r;
}
__device__ __forceinline__ ull d2u(double d){ return __double_as_longlong(d); }

// ---------------- scratch ----------------
__device__ float g_q[NM*HID];
__device__ float g_hmid[NM*HID];
__device__ float g_qk[NM*NH*HH];
__device__ float g_sb[NM*NH];
__device__ float g_dn[NM*NH];
__device__ float g_ue[NM*NH*HH];
__device__ float g_un[NM*NH*HH];
__device__ float g_mu[NM];
__device__ float g_rs[NM];
__device__ int   g_rowstart[NEGO+1];
// folded / composed weights
__device__ float g_Wqf[3*HID*HID];
__device__ float g_bqf[3*HID];
__device__ float g_W1f[3*HID*HID];
__device__ float g_b1f[3*HID];
__device__ float g_Wc[3*HID*HID];
__device__ float g_bc[3*HID];

// ---------------- segment offsets ----------------
__global__ void rowstart_kernel(const int* __restrict__ batch){
    int n = blockIdx.x*blockDim.x + threadIdx.x;
    if (n > NEGO) return;
    int lo = 0, hi = NEDGE;
    while (lo < hi){ int mid = (lo+hi)>>1; if (batch[mid] < n) lo = mid+1; else hi = mid; }
    g_rowstart[n] = lo;
}

// ---------------- per-row LN stats ----------------
__global__ __launch_bounds__(256) void stats_kernel(const float* __restrict__ x){
    int warp = threadIdx.x >> 5, lane = threadIdx.x & 31;
    int row = blockIdx.x*8 + warp;
    const float* xr = x + (size_t)row*HID;
    float s = 0.f, s2 = 0.f;
    #pragma unroll
    for (int k=0;k<8;k++){ float v = xr[lane + k*32]; s += v; s2 += v*v; }
    #pragma unroll
    for (int o=16;o>0;o>>=1){
        s  += __shfl_xor_sync(0xffffffffu, s,  o);
        s2 += __shfl_xor_sync(0xffffffffu, s2, o);
    }
    if (lane == 0){
        float mean = s*(1.f/HID);
        float var  = s2*(1.f/HID) - mean*mean;
        g_mu[row] = mean;
        g_rs[row] = rsqrtf(var + LNEPS);
    }
}

// ---------------- fold LN weights:  W' = diag(lnw)@W ; b' = lnb@W + b ----------------
__global__ __launch_bounds__(256) void foldln_kernel(
    const float* __restrict__ Wq, const float* __restrict__ bq,
    const float* __restrict__ ln1w, const float* __restrict__ ln1b,
    const float* __restrict__ W1, const float* __restrict__ b1,
    const float* __restrict__ ln2w, const float* __restrict__ ln2b)
{
    int jc = blockIdx.x*64, which = blockIdx.y, l = blockIdx.z;
    const float* W  = (which==0 ? Wq : W1) + (size_t)l*65536;
    const float* bb = (which==0 ? bq : b1) + l*256;
    const float* lw = (which==0 ? ln1w : ln2w) + l*256;
    const float* lb = (which==0 ? ln1b : ln2b) + l*256;
    float* Wo = (which==0 ? g_Wqf : g_W1f) + (size_t)l*65536;
    float* bo = (which==0 ? g_bqf : g_b1f) + l*256;
    __shared__ float lws[256], lbs[256], red[4][64];
    int t = threadIdx.x;
    lws[t] = lw[t]; lbs[t] = lb[t];
    __syncthreads();
    int j = jc + (t&63), kq = t>>6;
    float bacc = 0.f;
    for (int k=kq; k<256; k+=4){
        float w = W[(size_t)k*256 + j];
        Wo[(size_t)k*256 + j] = lws[k]*w;
        bacc += lbs[k]*w;
    }
    red[kq][t&63] = bacc;
    __syncthreads();
    if (t < 64)
        bo[jc+t] = red[0][t]+red[1][t]+red[2][t]+red[3][t] + bb[jc+t];
}

// ---------------- compose Wc = Wd @ W2 ----------------
__global__ __launch_bounds__(256) void compose_kernel(
    const float* __restrict__ Wd, const float* __restrict__ W2)
{
    int l = blockIdx.z;
    const float* A = Wd + (size_t)l*65536;
    const float* B = W2 + (size_t)l*65536;
    float* C = g_Wc + (size_t)l*65536;
    __shared__ float As[16*68];
    __shared__ float Bs[16*68];
    int t = threadIdx.x;
    int m0 = blockIdx.x*64, n0 = blockIdx.y*64;
    int ty = t>>4, tx = t&15;
    float acc[4][4];
    #pragma unroll
    for (int i=0;i<4;i++)
        #pragma unroll
        for (int j=0;j<4;j++) acc[i][j] = 0.f;
    int ar = t>>2, akc = (t&3)*4;
    int br = t>>4, bc = (t&15)*4;
    const float* Ap = A + (size_t)(m0+ar)*256 + akc;
    const float* Bp = B + (size_t)br*256 + n0 + bc;
    for (int k0=0;k0<256;k0+=16){
        float4 a4 = *(const float4*)(Ap + k0);
        float4 b4 = *(const float4*)(Bp + (size_t)k0*256);
        As[(akc+0)*68+ar] = a4.x; As[(akc+1)*68+ar] = a4.y;
        As[(akc+2)*68+ar] = a4.z; As[(akc+3)*68+ar] = a4.w;
        *(float4*)&Bs[br*68+bc] = b4;
        __syncthreads();
        #pragma unroll
        for (int k=0;k<16;k++){
            float4 av = *(float4*)&As[k*68+ty*4];
            float4 bv = *(float4*)&Bs[k*68+tx*4];
            float aa[4] = {av.x,av.y,av.z,av.w};
            float bb[4] = {bv.x,bv.y,bv.z,bv.w};
            #pragma unroll
            for (int i=0;i<4;i++)
                #pragma unroll
                for (int j=0;j<4;j++) acc[i][j] += aa[i]*bb[j];
        }
        __syncthreads();
    }
    #pragma unroll
    for (int i=0;i<4;i++){
        float4 o; o.x=acc[i][0]; o.y=acc[i][1]; o.z=acc[i][2]; o.w=acc[i][3];
        *(float4*)(C + (size_t)(m0+ty*4+i)*256 + n0 + tx*4) = o;
    }
}

// bc = bd @ W2 + b2
__global__ __launch_bounds__(256) void composebias_kernel(
    const float* __restrict__ bd, const float* __restrict__ W2, const float* __restrict__ b2)
{
    int jc = blockIdx.x*64, l = blockIdx.y;
    const float* B = W2 + (size_t)l*65536;
    __shared__ float bds[256], red[4][64];
    int t = threadIdx.x;
    bds[t] = bd[l*256 + t];
    __syncthreads();
    int j = jc + (t&63), kq = t>>6;
    float acc = 0.f;
    for (int k=kq;k<256;k+=4) acc += bds[k]*B[(size_t)k*256 + j];
    red[kq][t&63] = acc;
    __syncthreads();
    if (t < 64)
        g_bc[l*256 + jc + t] = red[0][t]+red[1][t]+red[2][t]+red[3][t] + b2[l*256+jc+t];
}

// ---------------- main GEMM: [6144,256] @ [256,256], f32x2 row-pair ----------------
__global__ __launch_bounds__(128) void gemm_kernel(
    int Asel, int Wsel, int layer, float* __restrict__ ego, int Csel, int relu)
{
    const float* A = (Asel==0) ? ego : g_hmid;
    const float* W = ((Wsel==0)? g_Wqf : (Wsel==1)? g_W1f : g_Wc) + (size_t)layer*65536;
    const float* bias = ((Wsel==0)? g_bqf : (Wsel==1)? g_b1f : g_bc) + layer*256;
    float* C = (Csel==0)? g_q : (Csel==1)? g_hmid : ego;

    __shared__ __align__(16) float As[16*68];
    __shared__ __align__(16) float Bs[16*68];

    int t = threadIdx.x;
    int m0 = blockIdx.x*64, n0 = blockIdx.y*64;
    int ty = t>>4, tx = t&15;

    ull acc[4][4];
    #pragma unroll
    for (int p=0;p<4;p++)
        #pragma unroll
        for (int c=0;c<4;c++) acc[p][c] = 0ull;

    int sr0 = t>>2, skc = (t&3)*4;   int sr1 = sr0 + 32;
    int br = t>>4, bc = (t&15)*4;    int br1 = br + 8;
    float mua=0.f, rsa=1.f, mub=0.f, rsb=1.f;
    if (Asel==0){
        mua = g_mu[m0+sr0]; rsa = g_rs[m0+sr0];
        mub = g_mu[m0+sr1]; rsb = g_rs[m0+sr1];
    }
    const float* Ap0 = A + (size_t)(m0+sr0)*256 + skc;
    const float* Ap1 = A + (size_t)(m0+sr1)*256 + skc;
    const float* Wp0 = W + (size_t)br*256 + n0 + bc;
    const float* Wp1 = W + (size_t)br1*256 + n0 + bc;

    for (int k0=0;k0<256;k0+=16){
        float4 a0 = *(const float4*)(Ap0 + k0);
        float4 a1 = *(const float4*)(Ap1 + k0);
        float4 w0 = *(const float4*)(Wp0 + (size_t)k0*256);
        float4 w1 = *(const float4*)(Wp1 + (size_t)k0*256);
        if (Asel==0){
            a0.x=(a0.x-mua)*rsa; a0.y=(a0.y-mua)*rsa; a0.z=(a0.z-mua)*rsa; a0.w=(a0.w-mua)*rsa;
            a1.x=(a1.x-mub)*rsb; a1.y=(a1.y-mub)*rsb; a1.z=(a1.z-mub)*rsb; a1.w=(a1.w-mub)*rsb;
        }
        __syncthreads();
        As[(skc+0)*68+sr0]=a0.x; As[(skc+1)*68+sr0]=a0.y;
        As[(skc+2)*68+sr0]=a0.z; As[(skc+3)*68+sr0]=a0.w;
        As[(skc+0)*68+sr1]=a1.x; As[(skc+1)*68+sr1]=a1.y;
        As[(skc+2)*68+sr1]=a1.z; As[(skc+3)*68+sr1]=a1.w;
        *(float4*)&Bs[br*68 + bc]  = w0;
        *(float4*)&Bs[br1*68 + bc] = w1;
        __syncthreads();
        #pragma unroll
        for (int k=0;k<16;k++){
            double2 av0 = *(const double2*)&As[k*68 + ty*8];
            double2 av1 = *(const double2*)&As[k*68 + ty*8 + 4];
            float4  bv  = *(const float4*)&Bs[k*68 + tx*4];
            ull a01=d2u(av0.x), a23=d2u(av0.y), a45=d2u(av1.x), a67=d2u(av1.y);
            ull b0=pack2(bv.x,bv.x), b1=pack2(bv.y,bv.y), b2=pack2(bv.z,bv.z), b3=pack2(bv.w,bv.w);
            fma2(acc[0][0],a01,b0); fma2(acc[0][1],a01,b1); fma2(acc[0][2],a01,b2); fma2(acc[0][3],a01,b3);
            fma2(acc[1][0],a23,b0); fma2(acc[1][1],a23,b1); fma2(acc[1][2],a23,b2); fma2(acc[1][3],a23,b3);
            fma2(acc[2][0],a45,b0); fma2(acc[2][1],a45,b1); fma2(acc[2][2],a45,b2); fma2(acc[2][3],a45,b3);
            fma2(acc[3][0],a67,b0); fma2(acc[3][1],a67,b1); fma2(acc[3][2],a67,b2); fma2(acc[3][3],a67,b3);
        }
    }

    float4 bb = *(const float4*)&bias[n0 + tx*4];
    #pragma unroll
    for (int p=0;p<4;p++){
        F2U u0,u1,u2,u3;
        u0.u=acc[p][0]; u1.u=acc[p][1]; u2.u=acc[p][2]; u3.u=acc[p][3];
        int re = m0 + ty*8 + 2*p;
        float4 oe, oo;
        oe.x=u0.f.x+bb.x; oe.y=u1.f.x+bb.y; oe.z=u2.f.x+bb.z; oe.w=u3.f.x+bb.w;
        oo.x=u0.f.y+bb.x; oo.y=u1.f.y+bb.y; oo.z=u2.f.y+bb.z; oo.w=u3.f.y+bb.w;
        if (relu){
            oe.x=fmaxf(oe.x,0.f); oe.y=fmaxf(oe.y,0.f); oe.z=fmaxf(oe.z,0.f); oe.w=fmaxf(oe.w,0.f);
            oo.x=fmaxf(oo.x,0.f); oo.y=fmaxf(oo.y,0.f); oo.z=fmaxf(oo.z,0.f); oo.w=fmaxf(oo.w,0.f);
        }
        float* cpe = C + (size_t)re*256 + n0 + tx*4;
        float* cpo = cpe + 256;
        if (Csel == 2){
            float4 r0 = *(const float4*)cpe;
            float4 r1 = *(const float4*)cpo;
            oe.x+=r0.x; oe.y+=r0.y; oe.z+=r0.z; oe.w+=r0.w;
            oo.x+=r1.x; oo.y+=r1.y; oo.z+=r1.z; oo.w+=r1.w;
        }
        *(float4*)cpe = oe;
        *(float4*)cpo = oo;
    }
}

// ---------------- qk fold per-head GEMM, f32x2 ----------------
__global__ __launch_bounds__(256) void qkfold_kernel(
    const float* __restrict__ Wk, const float* __restrict__ bk)
{
    int h = blockIdx.y;
    int nm0 = blockIdx.x*64;
    int t = threadIdx.x;
    __shared__ __align__(16) float Wks[32*129];
    __shared__ __align__(16) float qs[32*72];

    for (int idx=t; idx<128*32; idx+=256){
        int c = idx>>5, d = idx&31;
        Wks[d*129 + c] = Wk[(size_t)c*256 + h*32 + d];
    }
    for (int idx=t; idx<64*32; idx+=256){
        int r = idx>>5, d = idx&31;
        qs[d*72 + r] = g_q[(size_t)(nm0+r)*256 + h*32 + d];
    }
    __syncthreads();

    int tx = t&31, ty = t>>5;
    ull acc[4][4];
    #pragma unroll
    for (int p=0;p<4;p++)
        #pragma unroll
        for (int j=0;j<4;j++) acc[p][j] = 0ull;

    #pragma unroll 8
    for (int d=0; d<32; d++){
        double2 av0 = *(const double2*)&qs[d*72 + ty*8];
        double2 av1 = *(const double2*)&qs[d*72 + ty*8 + 4];
        ull a01=d2u(av0.x), a23=d2u(av0.y), a45=d2u(av1.x), a67=d2u(av1.y);
        float w0 = Wks[d*129 + tx];
        float w1 = Wks[d*129 + tx + 32];
        float w2 = Wks[d*129 + tx + 64];
        float w3 = Wks[d*129 + tx + 96];
        ull wd0=pack2(w0,w0), wd1=pack2(w1,w1), wd2=pack2(w2,w2), wd3=pack2(w3,w3);
        fma2(acc[0][0],a01,wd0); fma2(acc[0][1],a01,wd1); fma2(acc[0][2],a01,wd2); fma2(acc[0][3],a01,wd3);
        fma2(acc[1][0],a23,wd0); fma2(acc[1][1],a23,wd1); fma2(acc[1][2],a23,wd2); fma2(acc[1][3],a23,wd3);
        fma2(acc[2][0],a45,wd0); fma2(acc[2][1],a45,wd1); fma2(acc[2][2],a45,wd2); fma2(acc[2][3],a45,wd3);
        fma2(acc[3][0],a67,wd0); fma2(acc[3][1],a67,wd1); fma2(acc[3][2],a67,wd2); fma2(acc[3][3],a67,wd3);
    }

    #pragma unroll
    for (int p=0;p<4;p++){
        #pragma unroll
        for (int j=0;j<4;j++){
            F2U u; u.u = acc[p][j];
            float* base = g_qk + (size_t)(nm0 + ty*8 + 2*p)*1024 + h*128 + tx + 32*j;
            base[0]    = u.f.x;
            base[1024] = u.f.y;
        }
    }

    if (t < 64){
        float s = 0.f;
        #pragma unroll
        for (int d=0;d<32;d++) s += bk[h*32+d]*qs[d*72 + t];
        g_sb[(nm0+t)*NH + h] = s;
    }
}

// ---------------- FUSED attention: scores + online segment-softmax + weighted agg ----
// block per (n,m); 256 threads.
// Score phase: (el, h) = (t>>3, t&7) over 32-edge chunks.
// Reduce phase: warp w handles head w (8 warps).
// Accumulate phase: c = t&127 channel, half = t>>7 takes 16 of the 32 edges.
__global__ __launch_bounds__(256) void attn_kernel(
    const float* __restrict__ ef, const float* __restrict__ nf)
{
    int n = blockIdx.x, m = blockIdx.y;
    int nm = n*MM + m;
    int t = threadIdx.x;
    __shared__ __align__(16) float qs[8*132];
    __shared__ float sbs[8];
    __shared__ __align__(16) float efs[32*132];
    __shared__ __align__(16) float nfs[32*132];
    __shared__ __align__(16) float salph[32*8];
    __shared__ __align__(16) float sc_scale[8];
    __shared__ float run_m_s[8], run_s_s[8];

    #pragma unroll
    for (int j=0;j<4;j++){
        int o = t + j*256;
        qs[(o>>7)*132 + (o&127)] = g_qk[(size_t)nm*1024 + o];
    }
    if (t < 8){ sbs[t] = g_sb[nm*8+t]; run_m_s[t] = -INFINITY; run_s_s[t] = 0.f; }
    int e0 = g_rowstart[n], e1 = g_rowstart[n+1];
    int h = t & 7, el = t >> 3;
    int c = t & 127, half = t >> 7;
    int w = t >> 5, lane = t & 31;
    ull ue2[4], un2[4];
    #pragma unroll
    for (int i=0;i<4;i++){ ue2[i]=0ull; un2[i]=0ull; }
    __syncthreads();

    for (int e=e0; e<e1; e+=32){
        // ---- stage ef, nf chunk ----
        for (int idx=t; idx<32*128; idx+=256){
            int er = idx>>7, cc = idx&127;
            int ge = e + er;
            bool ok = (ge < e1);
            efs[er*132+cc] = ok ? ef[((size_t)ge*MM+m)*128 + cc] : 0.f;
            nfs[er*132+cc] = ok ? nf[((size_t)ge*MM+m)*128 + cc] : 0.f;
        }
        __syncthreads();
        // ---- scores ----
        {
            ull acca = 0ull, accb = 0ull;
            const double2* a = (const double2*)&efs[el*132];
            const double2* b = (const double2*)&qs[h*132];
            #pragma unroll
            for (int cc=0;cc<32;cc++){
                double2 av = a[cc], bv = b[cc];
                fma2(acca, d2u(av.x), d2u(bv.x));
                fma2(accb, d2u(av.y), d2u(bv.y));
            }
            F2U ua, ub; ua.u = acca; ub.u = accb;
            float s = sbs[h] + ua.f.x + ua.f.y + ub.f.x + ub.f.y;
            salph[t] = (e + el < e1) ? s : -INFINITY;   // salph[el*8+h] == salph[t]
        }
        __syncthreads();
        // ---- per-head online softmax update (warp w = head w) ----
        {
            float sv = salph[lane*8 + w];
            float mx = sv;
            #pragma unroll
            for (int o=16;o>0;o>>=1) mx = fmaxf(mx, __shfl_xor_sync(0xffffffffu, mx, o));
            float m_old = run_m_s[w];
            float m_new = fmaxf(m_old, mx);
            float ex = __expf(sv - m_new);              // -inf -> 0
            float sum = ex;
            #pragma unroll
            for (int o=16;o>0;o>>=1) sum += __shfl_xor_sync(0xffffffffu, sum, o);
            salph[lane*8 + w] = ex;
            if (lane == 0){
                float scl = (m_old == -INFINITY) ? 0.f : __expf(m_old - m_new);
                run_s_s[w] = run_s_s[w]*scl + sum;
                run_m_s[w] = m_new;
                sc_scale[w] = scl;
            }
        }
        __syncthreads();
        // ---- rescale accumulators + accumulate 16 edges (per half) ----
        {
            double2 sc0 = *(const double2*)&sc_scale[0];
            double2 sc1 = *(const double2*)&sc_scale[4];
            ull s01=d2u(sc0.x), s23=d2u(sc0.y), s45=d2u(sc1.x), s67=d2u(sc1.y);
            mul2(ue2[0],s01); mul2(ue2[1],s23); mul2(ue2[2],s45); mul2(ue2[3],s67);
            mul2(un2[0],s01); mul2(un2[1],s23); mul2(un2[2],s45); mul2(un2[3],s67);
            int eb = half*16;
            #pragma unroll
            for (int u=0;u<16;u++){
                int er = eb + u;
                float fe = efs[er*132 + c];
                float fn = nfs[er*132 + c];
                ull fed = pack2(fe,fe), fnd = pack2(fn,fn);
                double2 al0 = *(const double2*)&salph[er*8];
                double2 al1 = *(const double2*)&salph[er*8 + 4];
                ull a01=d2u(al0.x), a23=d2u(al0.y), a45=d2u(al1.x), a67=d2u(al1.y);
                fma2(ue2[0],a01,fed); fma2(ue2[1],a23,fed); fma2(ue2[2],a45,fed); fma2(ue2[3],a67,fed);
                fma2(un2[0],a01,fnd); fma2(un2[1],a23,fnd); fma2(un2[2],a45,fnd); fma2(un2[3],a67,fnd);
            }
        }
        __syncthreads();
    }

    // ---- merge halves via smem (reuse efs) ----
    ull* xch = (ull*)efs;   // 128 channels * 8 ull = 1024 ull = 8 KB <= efs
    if (half == 1){
        #pragma unroll
        for (int i=0;i<4;i++){ xch[c*8+i] = ue2[i]; xch[c*8+4+i] = un2[i]; }
    }
    __syncthreads();
    if (half == 0){
        float invd[8];
        #pragma unroll
        for (int hh=0;hh<8;hh++) invd[hh] = 1.f/(run_s_s[hh] + 1e-16f);
        #pragma unroll
        for (int i=0;i<4;i++){
            F2U a, b;
            a.u = ue2[i]; b.u = xch[c*8+i];
            float uex = (a.f.x + b.f.x)*invd[2*i];
            float uey = (a.f.y + b.f.y)*invd[2*i+1];
            a.u = un2[i]; b.u = xch[c*8+4+i];
            float unx = (a.f.x + b.f.x)*invd[2*i];
            float uny = (a.f.y + b.f.y)*invd[2*i+1];
            g_ue[((size_t)nm*NH + 2*i  )*HH + c] = uex;
            g_ue[((size_t)nm*NH + 2*i+1)*HH + c] = uey;
            g_un[((size_t)nm*NH + 2*i  )*HH + c] = unx;
            g_un[((size_t)nm*NH + 2*i+1)*HH + c] = uny;
        }
    }
    if (t < 8) g_dn[nm*8+t] = run_s_s[t];
}

// ---------------- v transform ----------------
__global__ __launch_bounds__(256) void vtrans_kernel(
    const float* __restrict__ Wv1, const float* __restrict__ bv1,
    const float* __restrict__ Wv2, const float* __restrict__ bv2,
    float* __restrict__ ego)
{
    int h = blockIdx.y;
    int nm0 = blockIdx.x*64;
    int t = threadIdx.x;
    __shared__ float W1s[32*132];
    __shared__ float W2s[32*132];
    for (int idx=t; idx<32*128; idx+=256){
        int j = idx & 31, p = idx >> 5;
        W1s[j*132+p] = Wv1[(size_t)p*256 + h*32 + j];
        W2s[j*132+p] = Wv2[(size_t)p*256 + h*32 + j];
    }
    __syncthreads();
    int ty = t>>5, j = t&31;
    float acc[8];
    #pragma unroll
    for (int i=0;i<8;i++) acc[i] = 0.f;
    const float* ue0 = g_ue + ((size_t)(nm0 + ty*8)*NH + h)*HH;
    const float* un0 = g_un + ((size_t)(nm0 + ty*8)*NH + h)*HH;
    #pragma unroll 4
    for (int p=0;p<128;p+=4){
        float4 w1 = *(const float4*)&W1s[j*132+p];
        float4 w2 = *(const float4*)&W2s[j*132+p];
        #pragma unroll
        for (int i=0;i<8;i++){
            float4 u1 = *(const float4*)(ue0 + (size_t)i*NH*HH + p);
            float4 u2 = *(const float4*)(un0 + (size_t)i*NH*HH + p);
            acc[i] += u1.x*w1.x + u1.y*w1.y + u1.z*w1.z + u1.w*w1.w
                    + u2.x*w2.x + u2.y*w2.y + u2.z*w2.z + u2.w*w2.w;
        }
    }
    float bsum = bv1[h*32+j] + bv2[h*32+j];
    #pragma unroll
    for (int i=0;i<8;i++){
        int nm = nm0 + ty*8 + i;
        float dn = g_dn[nm*NH + h];
        float asum = dn/(dn + 1e-16f);
        ego[(size_t)nm*256 + h*32 + j] += acc[i] + asum*bsum;
    }
}

// ---------------- driver ----------------
extern "C" void kernel_launch(void* const* d_in, const int* in_sizes, int n_in,
                              void* d_out, int out_size)
{
    const int*   batch = (const int*)d_in[0];
    const float* ego_f = (const float*)d_in[1];
    const float* ef    = (const float*)d_in[2];
    const float* nf    = (const float*)d_in[3];
    const float* Wk  = (const float*)d_in[4];
    const float* bk  = (const float*)d_in[5];
    const float* Wq  = (const float*)d_in[6];
    const float* bq  = (const float*)d_in[7];
    const float* Wv1 = (const float*)d_in[8];
    const float* bv1 = (const float*)d_in[9];
    const float* Wv2 = (const float*)d_in[10];
    const float* bv2 = (const float*)d_in[11];
    const float* ln1w= (const float*)d_in[12];
    const float* ln1b= (const float*)d_in[13];
    const float* ln2w= (const float*)d_in[14];
    const float* ln2b= (const float*)d_in[15];
    const float* W1  = (const float*)d_in[16];
    const float* b1  = (const float*)d_in[17];
    const float* W2  = (const float*)d_in[18];
    const float* b2  = (const float*)d_in[19];
    const float* Wd  = (const float*)d_in[20];
    const float* bd  = (const float*)d_in[21];
    float* ego = (float*)d_out;

    cudaMemcpyAsync(ego, ego_f, (size_t)NM*HID*sizeof(float),
                    cudaMemcpyDeviceToDevice, 0);
    rowstart_kernel<<<5, 256>>>(batch);
    foldln_kernel<<<dim3(4,2,3), 256>>>(Wq, bq, ln1w, ln1b, W1, b1, ln2w, ln2b);
    compose_kernel<<<dim3(4,4,3), 256>>>(Wd, W2);
    composebias_kernel<<<dim3(4,3), 256>>>(bd, W2, b2);

    dim3 ggemm(NM/64, HID/64);
    for (int l=0;l<3;l++){
        // --- attention block ---
        stats_kernel<<<NM/8, 256>>>(ego);
        gemm_kernel<<<ggemm, 128>>>(0, 0, l, ego, 0, 0);   // g_q = LN1(ego)@Wq' + bq'
        qkfold_kernel<<<dim3(NM/64, NH), 256>>>(Wk + (size_t)l*HH*HID, bk + l*HID);
        attn_kernel<<<dim3(NEGO, MM), 256>>>(ef, nf);      // fused scores+softmax+agg
        vtrans_kernel<<<dim3(NM/64, NH), 256>>>(Wv1 + (size_t)l*HH*HID, bv1 + l*HID,
                                                Wv2 + (size_t)l*HH*HID, bv2 + l*HID, ego);
        // --- ff block (Wd@W2 composed) ---
        stats_kernel<<<NM/8, 256>>>(ego);
        gemm_kernel<<<ggemm, 128>>>(0, 1, l, ego, 1, 1);   // g_hmid = relu(LN2(ego)@W1' + b1')
        gemm_kernel<<<ggemm, 128>>>(1, 2, l, ego, 2, 0);   // ego += g_hmid@Wc + bc
    }
    (void)in_sizes; (void)n_in; (void)out_size;
}